// round 9
// baseline (speedup 1.0000x reference)
#include <cuda_runtime.h>
#include <math.h>

#define BB 64
#define LL 128
#define HID 768
#define CDIM 256
#define SDIM 64
#define NOUT (CDIM + SDIM)      // 320
#define FEAT 321
#define NIT 30
#define EPSV 0.05f
#define L2E 1.4426950408889634f
#define INFN 3.0e38f
#define STH 640                  // sink threads per CTA

__device__ __forceinline__ float ex2a(float x) {
    float y; asm("ex2.approx.f32 %0, %1;" : "=f"(y) : "f"(x)); return y;
}
__device__ __forceinline__ float lg2a(float x) {
    float y; asm("lg2.approx.f32 %0, %1;" : "=f"(y) : "f"(x)); return y;
}

// ---------------- device scratch ---------------------------------------------
__device__ float g_Cs[BB * LL * LL];   // scaled cost (only [0,n)^2 valid)
__device__ float g_sq[BB * LL];
__device__ float g_rep[BB * 2 * HID];
__device__ float g_fused[BB * NOUT];
__device__ int   g_n0[BB], g_n1[BB];

// ---------------- K_prep ------------------------------------------------------
__global__ void __launch_bounds__(128) k_prep(
        const float* __restrict__ H, const int* __restrict__ tt,
        const int* __restrict__ am) {
    int b = blockIdx.x;
    int y = blockIdx.y;                    // 0..5
    int tid = threadIdx.x;                 // 128
    int d = y * 128 + tid;
    __shared__ float s_m0[LL], s_m1[LL];
    int a = am[b * LL + tid], t = tt[b * LL + tid];
    int f0 = (a == 1 && t == 0) ? 1 : 0;
    int f1 = (a == 1 && t == 1) ? 1 : 0;
    s_m0[tid] = (float)f0;
    s_m1[tid] = (float)f1;
    int n0 = __syncthreads_count(f0);
    int n1 = __syncthreads_count(f1);
    if (y == 0 && tid == 0) { g_n0[b] = n0; g_n1[b] = n1; }
    const float* Hb = H + (size_t)b * LL * HID;
    float a0 = 0.f, a1 = 0.f;
#pragma unroll 8
    for (int l = 0; l < LL; l++) {
        float h = Hb[l * HID + d];
        a0 += h * s_m0[l];
        a1 += h * s_m1[l];
    }
    float i0 = 1.f / fmaxf((float)n0, 1.f);
    float i1 = 1.f / fmaxf((float)n1, 1.f);
    g_rep[b * 2 * HID + d] = Hb[d];
    g_rep[b * 2 * HID + HID + d] = a0 * i0 - a1 * i1;
    int w = tid >> 5, lane = tid & 31;
    for (int r = y * 4 + w; r < LL; r += 24) {
        const float4* p = (const float4*)(Hb + (size_t)r * HID);
        float s = 0.f;
#pragma unroll
        for (int tq = 0; tq < HID / 128; tq++) {
            float4 v = p[lane + 32 * tq];
            s += v.x * v.x + v.y * v.y + v.z * v.z + v.w * v.w;
        }
#pragma unroll
        for (int o = 16; o; o >>= 1) s += __shfl_down_sync(0xffffffffu, s, o);
        if (lane == 0) g_sq[b * LL + r] = s;
    }
}

// ---------------- K_fused -----------------------------------------------------
#define FB 4
__global__ void __launch_bounds__(256) k_fused(
        const float* __restrict__ Wc, const float* __restrict__ bc,
        const float* __restrict__ Ws, const float* __restrict__ bs,
        const float* __restrict__ gate) {
    int b0 = blockIdx.y * FB;
    int w = threadIdx.x >> 5, lane = threadIdx.x & 31;
    int o = blockIdx.x * 8 + w;
    __shared__ __align__(16) float s_rep[FB][2 * HID];
    {
        const float4* g4 = (const float4*)(g_rep + (size_t)b0 * 2 * HID);
        float4* s4 = (float4*)&s_rep[0][0];
        for (int i = threadIdx.x; i < FB * (2 * HID) / 4; i += 256) s4[i] = g4[i];
    }
    __syncthreads();
    const float* W = (o < CDIM) ? (Wc + (size_t)o * 2 * HID)
                                : (Ws + (size_t)(o - CDIM) * 2 * HID);
    const float4* W4 = (const float4*)W;
    float acc[FB] = {};
#pragma unroll
    for (int t = 0; t < 12; t++) {
        float4 wv = W4[lane + 32 * t];
#pragma unroll
        for (int bb = 0; bb < FB; bb++) {
            float4 rv = *(const float4*)&s_rep[bb][4 * (lane + 32 * t)];
            acc[bb] += wv.x * rv.x + wv.y * rv.y + wv.z * rv.z + wv.w * rv.w;
        }
    }
#pragma unroll
    for (int off = 16; off; off >>= 1)
#pragma unroll
        for (int bb = 0; bb < FB; bb++)
            acc[bb] += __shfl_down_sync(0xffffffffu, acc[bb], off);
    if (lane == 0) {
        float gv = 1.f / (1.f + expf(-gate[0]));
        float bias = (o < CDIM) ? bc[o] : bs[o - CDIM];
        float sc = (o < CDIM) ? (1.f - gv) : gv;
#pragma unroll
        for (int bb = 0; bb < FB; bb++)
            g_fused[(b0 + bb) * NOUT + o] = (acc[bb] + bias) * sc;
    }
}

// ---------------- K_gram: symmetric 64x64 tiles -------------------------------
#define BT 64
#define BK 32
__global__ void __launch_bounds__(256) k_gram(const float* __restrict__ H) {
    const int TI[3] = {0, 0, 1};
    const int TJ[3] = {0, 1, 1};
    int b = blockIdx.y;
    int t = blockIdx.x;
    int ti = TI[t], tj = TJ[t];
    int i0 = ti * BT, j0 = tj * BT;
    int n = g_n0[b] + g_n1[b];
    if (i0 >= n || j0 >= n) return;
    __shared__ __align__(16) float sA[BK * (BT + 4)];
    __shared__ __align__(16) float sB[BK * (BT + 4)];
    int tid = threadIdx.x;
    int tx = tid & 15, ty = tid >> 4;
    float acc[4][4] = {};
    const float* Hb = H + (size_t)b * LL * HID;
    int lr = tid >> 3;
    int lc = tid & 7;
    for (int k0 = 0; k0 < HID; k0 += BK) {
#pragma unroll
        for (int h = 0; h < 2; h++) {
            int row = lr + 32 * h;
            float4 v = *(const float4*)(Hb + (size_t)(i0 + row) * HID + k0 + lc * 4);
            sA[(lc * 4 + 0) * (BT + 4) + row] = v.x;
            sA[(lc * 4 + 1) * (BT + 4) + row] = v.y;
            sA[(lc * 4 + 2) * (BT + 4) + row] = v.z;
            sA[(lc * 4 + 3) * (BT + 4) + row] = v.w;
            float4 u = *(const float4*)(Hb + (size_t)(j0 + row) * HID + k0 + lc * 4);
            sB[(lc * 4 + 0) * (BT + 4) + row] = u.x;
            sB[(lc * 4 + 1) * (BT + 4) + row] = u.y;
            sB[(lc * 4 + 2) * (BT + 4) + row] = u.z;
            sB[(lc * 4 + 3) * (BT + 4) + row] = u.w;
        }
        __syncthreads();
#pragma unroll
        for (int kk = 0; kk < BK; kk++) {
            float4 av = *(const float4*)&sA[kk * (BT + 4) + ty * 4];
            float4 bv = *(const float4*)&sB[kk * (BT + 4) + tx * 4];
            float ar[4] = {av.x, av.y, av.z, av.w};
            float br[4] = {bv.x, bv.y, bv.z, bv.w};
#pragma unroll
            for (int r = 0; r < 4; r++)
#pragma unroll
                for (int c = 0; c < 4; c++) acc[r][c] += ar[r] * br[c];
        }
        __syncthreads();
    }
    const float* sqb = g_sq + b * LL;
    float* out = g_Cs + (size_t)b * LL * LL;
#pragma unroll
    for (int r = 0; r < 4; r++) {
        int i = i0 + ty * 4 + r;
        float si = sqb[i];
#pragma unroll
        for (int c = 0; c < 4; c++) {
            int j = j0 + tx * 4 + c;
            float d2 = si + sqb[j] - 2.f * acc[r][c];
            float v = sqrtf(fmaxf(d2, 1e-6f)) * (L2E / EPSV);
            out[i * LL + j] = v;
            if (ti != tj) out[j * LL + i] = v;
        }
    }
}

// ---------------- K_sink: one CTA per batch, 3 variants in lockstep -----------
struct TMap {
    const float4* mat;
    const float4* u;
    float* w;
    float coef;
    int p4, sp, row, part, act;
};

__device__ __forceinline__ int align4i(int x) { return (x + 3) & ~3; }

// build thread mapping for one pass over 3 segments
__device__ void build_map(TMap& M,
                          const float* mats[3], const int p4s[3], const int rows[3],
                          const float* us[3], float* ws[3], const float coefs[3],
                          int tid) {
    int sp[3];
#pragma unroll
    for (int v = 0; v < 3; v++) sp[v] = (p4s[v] <= 6) ? 1 : 2;
    int used = align4i(sp[0] * rows[0]) + align4i(sp[1] * rows[1]) + align4i(sp[2] * rows[2]);
    // order desc by p4
    int o0 = 0, o1 = 1, o2 = 2, tmp;
    if (p4s[o0] < p4s[o1]) { tmp = o0; o0 = o1; o1 = tmp; }
    if (p4s[o1] < p4s[o2]) { tmp = o1; o1 = o2; o2 = tmp; }
    if (p4s[o0] < p4s[o1]) { tmp = o0; o0 = o1; o1 = tmp; }
    int ordv[3] = {o0, o1, o2};
#pragma unroll
    for (int k = 0; k < 3; k++) {
        int v = ordv[k];
        if (sp[v] == 2) {
            int nu = used - align4i(2 * rows[v]) + align4i(4 * rows[v]);
            if (nu <= STH) { sp[v] = 4; used = nu; }
        }
    }
    M.act = 0; M.sp = 1; M.part = 0; M.row = 0; M.p4 = 1;
    M.mat = (const float4*)mats[0]; M.u = (const float4*)us[0]; M.w = ws[0]; M.coef = 0.f;
    int base = 0;
#pragma unroll
    for (int v = 0; v < 3; v++) {
        int len = sp[v] * rows[v];
        if (tid >= base && tid < base + len) {
            int r = tid - base;
            M.act = 1;
            M.sp = sp[v];
            M.row = r / sp[v];
            M.part = r - M.row * sp[v];
            M.mat = (const float4*)mats[v];
            M.u = (const float4*)us[v];
            M.w = ws[v];
            M.coef = coefs[v];
            M.p4 = p4s[v];
        }
        base += align4i(len);
    }
}

__device__ __forceinline__ void run_pass(const TMap& M) {
    float m = -INFN, s = 0.f;
    if (M.act) {
        const float4* r4 = M.mat + (size_t)M.row * M.p4;
        float m0 = -INFN, m1 = -INFN;
        for (int j = M.part; j < M.p4; j += M.sp) {
            float4 c = r4[j], uu = M.u[j];
            m0 = fmaxf(m0, fmaxf(uu.x - c.x, uu.y - c.y));
            m1 = fmaxf(m1, fmaxf(uu.z - c.z, uu.w - c.w));
        }
        m = fmaxf(m0, m1);
        float s0 = 0.f, s1 = 0.f;
        for (int j = M.part; j < M.p4; j += M.sp) {
            float4 c = r4[j], uu = M.u[j];
            s0 += ex2a(uu.x - c.x - m) + ex2a(uu.y - c.y - m);
            s1 += ex2a(uu.z - c.z - m) + ex2a(uu.w - c.w - m);
        }
        s = s0 + s1;
    }
#pragma unroll
    for (int o = 1; o < 4; o <<= 1) {
        float om = __shfl_xor_sync(0xffffffffu, m, o);
        float os = __shfl_xor_sync(0xffffffffu, s, o);
        if (o < M.sp) {
            float nm = fmaxf(m, om);
            s = s * ex2a(m - nm) + os * ex2a(om - nm);
            m = nm;
        }
    }
    if (M.act && M.part == 0) M.w[M.row] = M.coef - (m + lg2a(s));
}

__global__ void __launch_bounds__(STH, 1) k_sink(
        const float* __restrict__ lnw, const float* __restrict__ lnb,
        const float* __restrict__ Wcls, const float* __restrict__ bcls,
        float* __restrict__ out) {
    extern __shared__ __align__(16) float sm[];
    __shared__ __align__(16) float s_u0[120], s_w0[56];
    __shared__ __align__(16) float s_u1[56],  s_w1[56];
    __shared__ __align__(16) float s_u2[120], s_w2[120];
    __shared__ float s_red[2 * (STH / 32)];
    int b = blockIdx.x;
    int tid = threadIdx.x;
    int n0 = g_n0[b], n1 = g_n1[b];
    int pa0 = ((n1 + 3) >> 2) | 1;   // v0 A pitch (cols n1)
    int pt0 = ((n0 + 3) >> 2) | 1;   // v0 T pitch (cols n0)
    int p1  = ((n0 + 3) >> 2) | 1;   // v1 pitch
    int p2  = ((n1 + 3) >> 2) | 1;   // v2 pitch
    // smem layout in float4 units
    int A0o = 0;
    int T0o = A0o + n0 * pa0;
    int A1o = T0o + n1 * pt0;
    int A2o = A1o + n0 * p1;
    int totf = (A2o + n1 * p2) * 4;
    for (int x = tid; x < totf; x += STH) sm[x] = INFN;
    float la0 = -lg2a((float)n0);    // row weight v0/v1
    float lb0 = -lg2a((float)n1);    // col weight v0, both v2
    if (tid < 120) {
        s_u0[tid] = (tid < n1) ? lb0 : 0.f;
        s_u2[tid] = (tid < n1) ? lb0 : 0.f;
        s_w2[tid] = 0.f;
        if (tid < 56) {
            s_w0[tid] = 0.f;
            s_u1[tid] = (tid < n0) ? la0 : 0.f;
            s_w1[tid] = 0.f;
        }
    }
    __syncthreads();
    // gather cost blocks
    {
        const float* src = g_Cs + (size_t)b * LL * LL;
        int j = tid & 127, q = tid >> 7;    // 5 row-streams
        if (j < n1) {
            for (int i = q; i < n0; i += 5) {         // v0: rows type0, cols type1
                float cv = src[i * LL + n0 + j];
                sm[A0o * 4 + i * pa0 * 4 + j] = cv;
                sm[T0o * 4 + j * pt0 * 4 + i] = cv;
            }
            for (int i = q; i < n1; i += 5)           // v2: type1 x type1
                sm[A2o * 4 + i * p2 * 4 + j] = src[(n0 + i) * LL + n0 + j];
        }
        if (j < n0) {
            for (int i = q; i < n0; i += 5)           // v1: type0 x type0
                sm[A1o * 4 + i * p1 * 4 + j] = src[i * LL + j];
        }
    }
    __syncthreads();
    // build pass maps
    TMap MA, MB;
    {
        const float* matsA[3] = {sm + A0o * 4, sm + A1o * 4, sm + A2o * 4};
        const int p4A[3] = {pa0, p1, p2};
        const int rA[3] = {n0, n0, n1};
        const float* uA[3] = {s_u0, s_u1, s_u2};
        float* wA[3] = {s_w0, s_w1, s_w2};
        const float cA[3] = {la0, la0, lb0};
        build_map(MA, matsA, p4A, rA, uA, wA, cA, tid);
        const float* matsB[3] = {sm + T0o * 4, sm + A1o * 4, sm + A2o * 4};
        const int p4B[3] = {pt0, p1, p2};
        const int rB[3] = {n1, n0, n1};
        const float* uB[3] = {s_w0, s_w1, s_w2};
        float* wB[3] = {s_u0, s_u1, s_u2};
        const float cB[3] = {lb0, la0, lb0};
        build_map(MB, matsB, p4B, rB, uB, wB, cB, tid);
    }
    for (int it = 0; it < NIT; it++) {
        run_pass(MA);
        __syncthreads();
        run_pass(MB);
        __syncthreads();
    }
    // d_ot = v0 - 0.5*(v1 + v2), value_v = <a,f> + <b,g>
    float acc = 0.f;
    float in0 = 1.f / (float)n0, in1 = 1.f / (float)n1;
    if (tid < n0)
        acc += ((s_w0[tid] - la0) - 0.5f * ((s_w1[tid] - la0) + (s_u1[tid] - la0))) * in0;
    if (tid < n1)
        acc += ((s_u0[tid] - lb0) - 0.5f * ((s_w2[tid] - lb0) + (s_u2[tid] - lb0))) * in1;
    acc *= (EPSV / L2E);
#pragma unroll
    for (int o = 16; o; o >>= 1) acc += __shfl_down_sync(0xffffffffu, acc, o);
    int wid = tid >> 5;
    if ((tid & 31) == 0) s_red[wid] = acc;
    __syncthreads();
    __shared__ float s_dot;
    if (tid == 0) {
        float d = 0.f;
#pragma unroll
        for (int i = 0; i < STH / 32; i++) d += s_red[i];
        s_dot = d;
    }
    __syncthreads();
    // ---- final head ----
    __shared__ float s_feat[FEAT];
    float dot = s_dot;
    for (int i = tid; i < FEAT; i += STH)
        s_feat[i] = (i < NOUT) ? g_fused[b * NOUT + i] : dot;
    __syncthreads();
    float s = 0.f, s2 = 0.f;
    for (int i = tid; i < FEAT; i += STH) {
        float x = s_feat[i];
        s += x; s2 += x * x;
    }
#pragma unroll
    for (int o = 16; o; o >>= 1) {
        s  += __shfl_down_sync(0xffffffffu, s, o);
        s2 += __shfl_down_sync(0xffffffffu, s2, o);
    }
    if ((tid & 31) == 0) { s_red[wid] = s; s_red[STH / 32 + wid] = s2; }
    __syncthreads();
    float S = 0.f, S2 = 0.f;
#pragma unroll
    for (int i = 0; i < STH / 32; i++) { S += s_red[i]; S2 += s_red[STH / 32 + i]; }
    float mu = S / (float)FEAT;
    float var = S2 / (float)FEAT - mu * mu;
    float rstd = rsqrtf(var + 1e-5f);
    float a0 = 0.f, a1 = 0.f;
    for (int i = tid; i < FEAT; i += STH) {
        float h = (s_feat[i] - mu) * rstd * lnw[i] + lnb[i];
        a0 += h * Wcls[i];
        a1 += h * Wcls[FEAT + i];
    }
#pragma unroll
    for (int o = 16; o; o >>= 1) {
        a0 += __shfl_down_sync(0xffffffffu, a0, o);
        a1 += __shfl_down_sync(0xffffffffu, a1, o);
    }
    __syncthreads();
    if ((tid & 31) == 0) { s_red[wid] = a0; s_red[STH / 32 + wid] = a1; }
    __syncthreads();
    if (tid == 0) {
        float r0 = 0.f, r1 = 0.f;
#pragma unroll
        for (int i = 0; i < STH / 32; i++) { r0 += s_red[i]; r1 += s_red[STH / 32 + i]; }
        out[b * 2 + 0] = r0 + bcls[0];
        out[b * 2 + 1] = r1 + bcls[1];
    }
}

// ---------------- launch --------------------------------------------------------
#define SINK_SMEM 74752    // >= 4*4*(n0*pa0+n1*pt0+n0*p1+n1*p2) worst ~72.7KB

extern "C" void kernel_launch(void* const* d_in, const int* in_sizes, int n_in,
                              void* d_out, int out_size) {
    const float* H    = (const float*)d_in[0];
    const int*   tt   = (const int*)d_in[1];
    const int*   am   = (const int*)d_in[2];
    const float* Wc   = (const float*)d_in[3];
    const float* bc   = (const float*)d_in[4];
    const float* Ws   = (const float*)d_in[5];
    const float* bs   = (const float*)d_in[6];
    const float* gate = (const float*)d_in[7];
    const float* lnw  = (const float*)d_in[8];
    const float* lnb  = (const float*)d_in[9];
    const float* Wcls = (const float*)d_in[10];
    const float* bcls = (const float*)d_in[11];
    float* out = (float*)d_out;

    cudaFuncSetAttribute(k_sink, cudaFuncAttributeMaxDynamicSharedMemorySize, SINK_SMEM);

    k_prep<<<dim3(BB, 6), 128>>>(H, tt, am);
    k_gram<<<dim3(3, BB), 256>>>(H);
    k_fused<<<dim3(40, BB / FB), 256>>>(Wc, bc, Ws, bs, gate);
    k_sink<<<BB, STH, SINK_SMEM>>>(lnw, lnb, Wcls, bcls, out);
}

// round 10
// speedup vs baseline: 1.0937x; 1.0937x over previous
#include <cuda_runtime.h>
#include <math.h>

#define BB 64
#define LL 128
#define HID 768
#define CDIM 256
#define SDIM 64
#define NOUT (CDIM + SDIM)      // 320
#define FEAT 321
#define NIT 30
#define EPSV 0.05f
#define L2E 1.4426950408889634f
#define INFN 3.0e38f
#define STH 512

__device__ __forceinline__ float ex2a(float x) {
    float y; asm("ex2.approx.f32 %0, %1;" : "=f"(y) : "f"(x)); return y;
}
__device__ __forceinline__ float lg2a(float x) {
    float y; asm("lg2.approx.f32 %0, %1;" : "=f"(y) : "f"(x)); return y;
}

// ---------------- device scratch ---------------------------------------------
__device__ float g_Cs[BB * LL * LL];   // scaled cost (only [0,n)^2 valid)
__device__ float g_sq[BB * LL];
__device__ float g_rep[BB * 2 * HID];
__device__ float g_fused[BB * NOUT];
__device__ float g_sink[3 * BB];
__device__ int   g_n0[BB], g_n1[BB];
__device__ int   g_cnt[BB];

// ---------------- K_prep ------------------------------------------------------
__global__ void __launch_bounds__(128) k_prep(
        const float* __restrict__ H, const int* __restrict__ tt,
        const int* __restrict__ am) {
    int b = blockIdx.x;
    int y = blockIdx.y;                    // 0..5
    int tid = threadIdx.x;                 // 128
    int d = y * 128 + tid;
    __shared__ float s_m0[LL], s_m1[LL];
    int a = am[b * LL + tid], t = tt[b * LL + tid];
    int f0 = (a == 1 && t == 0) ? 1 : 0;
    int f1 = (a == 1 && t == 1) ? 1 : 0;
    s_m0[tid] = (float)f0;
    s_m1[tid] = (float)f1;
    int n0 = __syncthreads_count(f0);
    int n1 = __syncthreads_count(f1);
    if (y == 0 && tid == 0) { g_n0[b] = n0; g_n1[b] = n1; g_cnt[b] = 0; }
    const float* Hb = H + (size_t)b * LL * HID;
    float a0 = 0.f, a1 = 0.f;
#pragma unroll 8
    for (int l = 0; l < LL; l++) {
        float h = Hb[l * HID + d];
        a0 += h * s_m0[l];
        a1 += h * s_m1[l];
    }
    float i0 = 1.f / fmaxf((float)n0, 1.f);
    float i1 = 1.f / fmaxf((float)n1, 1.f);
    g_rep[b * 2 * HID + d] = Hb[d];
    g_rep[b * 2 * HID + HID + d] = a0 * i0 - a1 * i1;
    int w = tid >> 5, lane = tid & 31;
    for (int r = y * 4 + w; r < LL; r += 24) {
        const float4* p = (const float4*)(Hb + (size_t)r * HID);
        float s = 0.f;
#pragma unroll
        for (int tq = 0; tq < HID / 128; tq++) {
            float4 v = p[lane + 32 * tq];
            s += v.x * v.x + v.y * v.y + v.z * v.z + v.w * v.w;
        }
#pragma unroll
        for (int o = 16; o; o >>= 1) s += __shfl_down_sync(0xffffffffu, s, o);
        if (lane == 0) g_sq[b * LL + r] = s;
    }
}

// ---------------- K_fused -----------------------------------------------------
#define FB 4
__global__ void __launch_bounds__(256) k_fused(
        const float* __restrict__ Wc, const float* __restrict__ bc,
        const float* __restrict__ Ws, const float* __restrict__ bs,
        const float* __restrict__ gate) {
    int b0 = blockIdx.y * FB;
    int w = threadIdx.x >> 5, lane = threadIdx.x & 31;
    int o = blockIdx.x * 8 + w;
    __shared__ __align__(16) float s_rep[FB][2 * HID];
    {
        const float4* g4 = (const float4*)(g_rep + (size_t)b0 * 2 * HID);
        float4* s4 = (float4*)&s_rep[0][0];
        for (int i = threadIdx.x; i < FB * (2 * HID) / 4; i += 256) s4[i] = g4[i];
    }
    __syncthreads();
    const float* W = (o < CDIM) ? (Wc + (size_t)o * 2 * HID)
                                : (Ws + (size_t)(o - CDIM) * 2 * HID);
    const float4* W4 = (const float4*)W;
    float acc[FB] = {};
#pragma unroll
    for (int t = 0; t < 12; t++) {
        float4 wv = W4[lane + 32 * t];
#pragma unroll
        for (int bb = 0; bb < FB; bb++) {
            float4 rv = *(const float4*)&s_rep[bb][4 * (lane + 32 * t)];
            acc[bb] += wv.x * rv.x + wv.y * rv.y + wv.z * rv.z + wv.w * rv.w;
        }
    }
#pragma unroll
    for (int off = 16; off; off >>= 1)
#pragma unroll
        for (int bb = 0; bb < FB; bb++)
            acc[bb] += __shfl_down_sync(0xffffffffu, acc[bb], off);
    if (lane == 0) {
        float gv = 1.f / (1.f + expf(-gate[0]));
        float bias = (o < CDIM) ? bc[o] : bs[o - CDIM];
        float sc = (o < CDIM) ? (1.f - gv) : gv;
#pragma unroll
        for (int bb = 0; bb < FB; bb++)
            g_fused[(b0 + bb) * NOUT + o] = (acc[bb] + bias) * sc;
    }
}

// ---------------- K_gram: symmetric 64x64 tiles -------------------------------
#define BT 64
#define BK 32
__global__ void __launch_bounds__(256) k_gram(const float* __restrict__ H) {
    const int TI[3] = {0, 0, 1};
    const int TJ[3] = {0, 1, 1};
    int b = blockIdx.y;
    int t = blockIdx.x;
    int ti = TI[t], tj = TJ[t];
    int i0 = ti * BT, j0 = tj * BT;
    int n = g_n0[b] + g_n1[b];
    if (i0 >= n || j0 >= n) return;
    __shared__ __align__(16) float sA[BK * (BT + 4)];
    __shared__ __align__(16) float sB[BK * (BT + 4)];
    int tid = threadIdx.x;
    int tx = tid & 15, ty = tid >> 4;
    float acc[4][4] = {};
    const float* Hb = H + (size_t)b * LL * HID;
    int lr = tid >> 3;
    int lc = tid & 7;
    for (int k0 = 0; k0 < HID; k0 += BK) {
#pragma unroll
        for (int h = 0; h < 2; h++) {
            int row = lr + 32 * h;
            float4 v = *(const float4*)(Hb + (size_t)(i0 + row) * HID + k0 + lc * 4);
            sA[(lc * 4 + 0) * (BT + 4) + row] = v.x;
            sA[(lc * 4 + 1) * (BT + 4) + row] = v.y;
            sA[(lc * 4 + 2) * (BT + 4) + row] = v.z;
            sA[(lc * 4 + 3) * (BT + 4) + row] = v.w;
            float4 u = *(const float4*)(Hb + (size_t)(j0 + row) * HID + k0 + lc * 4);
            sB[(lc * 4 + 0) * (BT + 4) + row] = u.x;
            sB[(lc * 4 + 1) * (BT + 4) + row] = u.y;
            sB[(lc * 4 + 2) * (BT + 4) + row] = u.z;
            sB[(lc * 4 + 3) * (BT + 4) + row] = u.w;
        }
        __syncthreads();
#pragma unroll
        for (int kk = 0; kk < BK; kk++) {
            float4 av = *(const float4*)&sA[kk * (BT + 4) + ty * 4];
            float4 bv = *(const float4*)&sB[kk * (BT + 4) + tx * 4];
            float ar[4] = {av.x, av.y, av.z, av.w};
            float br[4] = {bv.x, bv.y, bv.z, bv.w};
#pragma unroll
            for (int r = 0; r < 4; r++)
#pragma unroll
                for (int c = 0; c < 4; c++) acc[r][c] += ar[r] * br[c];
        }
        __syncthreads();
    }
    const float* sqb = g_sq + b * LL;
    float* out = g_Cs + (size_t)b * LL * LL;
#pragma unroll
    for (int r = 0; r < 4; r++) {
        int i = i0 + ty * 4 + r;
        float si = sqb[i];
#pragma unroll
        for (int c = 0; c < 4; c++) {
            int j = j0 + tx * 4 + c;
            float d2 = si + sqb[j] - 2.f * acc[r][c];
            float v = sqrtf(fmaxf(d2, 1e-6f)) * (L2E / EPSV);
            out[i * LL + j] = v;
            if (ti != tj) out[j * LL + i] = v;
        }
    }
}

// ---------------- K_sink: 512-thread all-row-pass Sinkhorn + fused final ------
__device__ __forceinline__ void lse_pass(const float* __restrict__ M, int p4, int nr,
                                         const float* __restrict__ u,
                                         float* __restrict__ outv,
                                         float coef, int tid) {
    int sp = (nr <= 32) ? 16 : (nr <= 64) ? 8 : 4;   // threads per row (512 thr)
    int row = tid / sp, part = tid - row * sp;
    float m = -INFN, s = 0.f;
    if (row < nr) {
        const float4* r4 = (const float4*)M + (size_t)row * p4;
        const float4* u4 = (const float4*)u;
        float m0 = -INFN, m1 = -INFN;
        for (int j = part; j < p4; j += sp) {
            float4 c = r4[j], uu = u4[j];
            m0 = fmaxf(m0, fmaxf(uu.x - c.x, uu.y - c.y));
            m1 = fmaxf(m1, fmaxf(uu.z - c.z, uu.w - c.w));
        }
        m = fmaxf(m0, m1);
        float s0 = 0.f, s1 = 0.f;
        for (int j = part; j < p4; j += sp) {
            float4 c = r4[j], uu = u4[j];
            s0 += ex2a(uu.x - c.x - m) + ex2a(uu.y - c.y - m);
            s1 += ex2a(uu.z - c.z - m) + ex2a(uu.w - c.w - m);
        }
        s = s0 + s1;
    }
#pragma unroll
    for (int o = 1; o < 16; o <<= 1) {
        if (o < sp) {
            float om = __shfl_xor_sync(0xffffffffu, m, o);
            float os = __shfl_xor_sync(0xffffffffu, s, o);
            float nm = fmaxf(m, om);
            s = s * ex2a(m - nm) + os * ex2a(om - nm);
            m = nm;
        }
    }
    if (row < nr && part == 0) outv[row] = coef - (m + lg2a(s));
}

__global__ void __launch_bounds__(STH) k_sink(
        const float* __restrict__ lnw, const float* __restrict__ lnb,
        const float* __restrict__ Wcls, const float* __restrict__ bcls,
        float* __restrict__ out) {
    extern __shared__ __align__(16) float sm[];
    __shared__ __align__(16) float s_u[128], s_w[128];
    __shared__ float s_red[2 * (STH / 32)];
    __shared__ int s_last;
    int bx = blockIdx.x;
    // wave order: v2 (largest) first, then v0, then v1
    int vg = bx / BB;
    int b = bx - vg * BB;
    int v = (vg == 0) ? 2 : (vg == 1) ? 0 : 1;
    int n0 = g_n0[b], n1 = g_n1[b];
    int ra, na, rb, nb;
    if (v == 0)      { ra = 0;  na = n0; rb = n0; nb = n1; }
    else if (v == 1) { ra = 0;  na = n0; rb = 0;  nb = n0; }
    else             { ra = n0; na = n1; rb = n0; nb = n1; }
    int tid = threadIdx.x;           // 512
    int pa4 = ((nb + 3) >> 2) | 1;   // float4 pitch of A (na x nb), odd
    int pt4 = ((na + 3) >> 2) | 1;   // float4 pitch of AT (nb x na), odd
    float* A = sm;
    float* T = (v == 0) ? (sm + na * pa4 * 4) : sm;   // symmetric: T == A
    int ptu4 = (v == 0) ? pt4 : pa4;
    {
        int totA = na * pa4 * 4;
        int totT = (v == 0) ? nb * pt4 * 4 : 0;
        for (int x = tid; x < totA; x += STH) A[x] = INFN;
        for (int x = tid; x < totT; x += STH) T[x] = INFN;
    }
    __syncthreads();
    // gather compact cost block (and transpose for cross variant); 4 row-groups
    const float* src = g_Cs + (size_t)b * LL * LL;
    {
        int j = tid & 127, q = tid >> 7;   // q in {0..3}
        if (j < nb) {
            for (int i = q; i < na; i += 4) {
                float cv = src[(ra + i) * LL + rb + j];
                A[i * pa4 * 4 + j] = cv;
                if (v == 0) T[j * pt4 * 4 + i] = cv;
            }
        }
    }
    float la2 = -lg2a((float)na);
    float lb2 = -lg2a((float)nb);
    if (tid < 128) {
        s_u[tid] = (tid < nb) ? lb2 : -INFN;
        s_w[tid] = -INFN;
    }
    __syncthreads();
    for (int it = 0; it < NIT; it++) {
        lse_pass(A, pa4, na, s_u, s_w, la2, tid);
        __syncthreads();
        lse_pass(T, ptu4, nb, s_w, s_u, lb2, tid);
        __syncthreads();
    }
    float val = 0.f;
    if (tid < na) val += (s_w[tid] - la2) * (1.f / (float)na);
    if (tid < nb) val += (s_u[tid] - lb2) * (1.f / (float)nb);
    val *= (EPSV / L2E);
#pragma unroll
    for (int o = 16; o; o >>= 1) val += __shfl_down_sync(0xffffffffu, val, o);
    int wid = tid >> 5;
    if ((tid & 31) == 0) s_red[wid] = val;
    __syncthreads();
    if (tid == 0) {
        float acc = 0.f;
#pragma unroll
        for (int i = 0; i < STH / 32; i++) acc += s_red[i];
        g_sink[v * BB + b] = acc;
        __threadfence();
        int old = atomicAdd(&g_cnt[b], 1);
        s_last = (old == 2) ? 1 : 0;
    }
    __syncthreads();
    if (!s_last) return;
    __threadfence();
    // ---- fused final head for batch b ----
    __shared__ float s_feat[FEAT];
    float dot = g_sink[b] - 0.5f * (g_sink[BB + b] + g_sink[2 * BB + b]);
    for (int i = tid; i < FEAT; i += STH)
        s_feat[i] = (i < NOUT) ? g_fused[b * NOUT + i] : dot;
    __syncthreads();
    float s = 0.f, s2 = 0.f;
    for (int i = tid; i < FEAT; i += STH) {
        float x = s_feat[i];
        s += x; s2 += x * x;
    }
#pragma unroll
    for (int o = 16; o; o >>= 1) {
        s  += __shfl_down_sync(0xffffffffu, s, o);
        s2 += __shfl_down_sync(0xffffffffu, s2, o);
    }
    if ((tid & 31) == 0) { s_red[wid] = s; s_red[STH / 32 + wid] = s2; }
    __syncthreads();
    float S = 0.f, S2 = 0.f;
#pragma unroll
    for (int i = 0; i < STH / 32; i++) { S += s_red[i]; S2 += s_red[STH / 32 + i]; }
    float mu = S / (float)FEAT;
    float var = S2 / (float)FEAT - mu * mu;
    float rstd = rsqrtf(var + 1e-5f);
    float a0 = 0.f, a1 = 0.f;
    for (int i = tid; i < FEAT; i += STH) {
        float h = (s_feat[i] - mu) * rstd * lnw[i] + lnb[i];
        a0 += h * Wcls[i];
        a1 += h * Wcls[FEAT + i];
    }
#pragma unroll
    for (int o = 16; o; o >>= 1) {
        a0 += __shfl_down_sync(0xffffffffu, a0, o);
        a1 += __shfl_down_sync(0xffffffffu, a1, o);
    }
    __syncthreads();
    if ((tid & 31) == 0) { s_red[wid] = a0; s_red[STH / 32 + wid] = a1; }
    __syncthreads();
    if (tid == 0) {
        float r0 = 0.f, r1 = 0.f;
#pragma unroll
        for (int i = 0; i < STH / 32; i++) { r0 += s_red[i]; r1 += s_red[STH / 32 + i]; }
        out[b * 2 + 0] = r0 + bcls[0];
        out[b * 2 + 1] = r1 + bcls[1];
    }
}

// ---------------- launch --------------------------------------------------------
#define SINK_SMEM (112 * 116 * 4)   // worst case: v2 with n1=112, pitch4=29

extern "C" void kernel_launch(void* const* d_in, const int* in_sizes, int n_in,
                              void* d_out, int out_size) {
    const float* H    = (const float*)d_in[0];
    const int*   tt   = (const int*)d_in[1];
    const int*   am   = (const int*)d_in[2];
    const float* Wc   = (const float*)d_in[3];
    const float* bc   = (const float*)d_in[4];
    const float* Ws   = (const float*)d_in[5];
    const float* bs   = (const float*)d_in[6];
    const float* gate = (const float*)d_in[7];
    const float* lnw  = (const float*)d_in[8];
    const float* lnb  = (const float*)d_in[9];
    const float* Wcls = (const float*)d_in[10];
    const float* bcls = (const float*)d_in[11];
    float* out = (float*)d_out;

    cudaFuncSetAttribute(k_sink, cudaFuncAttributeMaxDynamicSharedMemorySize, SINK_SMEM);

    k_prep<<<dim3(BB, 6), 128>>>(H, tt, am);
    k_gram<<<dim3(3, BB), 256>>>(H);
    k_fused<<<dim3(40, BB / FB), 256>>>(Wc, bc, Ws, bs, gate);
    k_sink<<<3 * BB, STH, SINK_SMEM>>>(lnw, lnb, Wcls, bcls, out);
}

// round 11
// speedup vs baseline: 1.2569x; 1.1491x over previous
#include <cuda_runtime.h>
#include <math.h>

#define BB 64
#define LL 128
#define HID 768
#define CDIM 256
#define SDIM 64
#define NOUT (CDIM + SDIM)      // 320
#define FEAT 321
#define NIT 30
#define EPSV 0.05f
#define L2E 1.4426950408889634f
#define INFN 3.0e38f
#define STH 256

__device__ __forceinline__ float ex2a(float x) {
    float y; asm("ex2.approx.f32 %0, %1;" : "=f"(y) : "f"(x)); return y;
}
__device__ __forceinline__ float lg2a(float x) {
    float y; asm("lg2.approx.f32 %0, %1;" : "=f"(y) : "f"(x)); return y;
}

// ---------------- device scratch ---------------------------------------------
__device__ float g_Cs[BB * LL * LL];   // scaled cost (only [0,n)^2 valid)
__device__ float g_sq[BB * LL];
__device__ float g_rep[BB * 2 * HID];
__device__ float g_fused[BB * NOUT];
__device__ float g_sink[3 * BB];
__device__ int   g_n0[BB], g_n1[BB];
__device__ int   g_cnt[BB];

// ---------------- K_prep ------------------------------------------------------
__global__ void __launch_bounds__(128) k_prep(
        const float* __restrict__ H, const int* __restrict__ tt,
        const int* __restrict__ am) {
    int b = blockIdx.x;
    int y = blockIdx.y;                    // 0..5
    int tid = threadIdx.x;                 // 128
    int d = y * 128 + tid;
    __shared__ float s_m0[LL], s_m1[LL];
    int a = am[b * LL + tid], t = tt[b * LL + tid];
    int f0 = (a == 1 && t == 0) ? 1 : 0;
    int f1 = (a == 1 && t == 1) ? 1 : 0;
    s_m0[tid] = (float)f0;
    s_m1[tid] = (float)f1;
    int n0 = __syncthreads_count(f0);
    int n1 = __syncthreads_count(f1);
    if (y == 0 && tid == 0) { g_n0[b] = n0; g_n1[b] = n1; g_cnt[b] = 0; }
    const float* Hb = H + (size_t)b * LL * HID;
    float a0 = 0.f, a1 = 0.f;
#pragma unroll 8
    for (int l = 0; l < LL; l++) {
        float h = Hb[l * HID + d];
        a0 += h * s_m0[l];
        a1 += h * s_m1[l];
    }
    float i0 = 1.f / fmaxf((float)n0, 1.f);
    float i1 = 1.f / fmaxf((float)n1, 1.f);
    g_rep[b * 2 * HID + d] = Hb[d];
    g_rep[b * 2 * HID + HID + d] = a0 * i0 - a1 * i1;
    int w = tid >> 5, lane = tid & 31;
    for (int r = y * 4 + w; r < LL; r += 24) {
        const float4* p = (const float4*)(Hb + (size_t)r * HID);
        float s = 0.f;
#pragma unroll
        for (int tq = 0; tq < HID / 128; tq++) {
            float4 v = p[lane + 32 * tq];
            s += v.x * v.x + v.y * v.y + v.z * v.z + v.w * v.w;
        }
#pragma unroll
        for (int o = 16; o; o >>= 1) s += __shfl_down_sync(0xffffffffu, s, o);
        if (lane == 0) g_sq[b * LL + r] = s;
    }
}

// ---------------- K_fused -----------------------------------------------------
#define FB 4
__global__ void __launch_bounds__(256) k_fused(
        const float* __restrict__ Wc, const float* __restrict__ bc,
        const float* __restrict__ Ws, const float* __restrict__ bs,
        const float* __restrict__ gate) {
    int b0 = blockIdx.y * FB;
    int w = threadIdx.x >> 5, lane = threadIdx.x & 31;
    int o = blockIdx.x * 8 + w;
    __shared__ __align__(16) float s_rep[FB][2 * HID];
    {
        const float4* g4 = (const float4*)(g_rep + (size_t)b0 * 2 * HID);
        float4* s4 = (float4*)&s_rep[0][0];
        for (int i = threadIdx.x; i < FB * (2 * HID) / 4; i += 256) s4[i] = g4[i];
    }
    __syncthreads();
    const float* W = (o < CDIM) ? (Wc + (size_t)o * 2 * HID)
                                : (Ws + (size_t)(o - CDIM) * 2 * HID);
    const float4* W4 = (const float4*)W;
    float acc[FB] = {};
#pragma unroll
    for (int t = 0; t < 12; t++) {
        float4 wv = W4[lane + 32 * t];
#pragma unroll
        for (int bb = 0; bb < FB; bb++) {
            float4 rv = *(const float4*)&s_rep[bb][4 * (lane + 32 * t)];
            acc[bb] += wv.x * rv.x + wv.y * rv.y + wv.z * rv.z + wv.w * rv.w;
        }
    }
#pragma unroll
    for (int off = 16; off; off >>= 1)
#pragma unroll
        for (int bb = 0; bb < FB; bb++)
            acc[bb] += __shfl_down_sync(0xffffffffu, acc[bb], off);
    if (lane == 0) {
        float gv = 1.f / (1.f + expf(-gate[0]));
        float bias = (o < CDIM) ? bc[o] : bs[o - CDIM];
        float sc = (o < CDIM) ? (1.f - gv) : gv;
#pragma unroll
        for (int bb = 0; bb < FB; bb++)
            g_fused[(b0 + bb) * NOUT + o] = (acc[bb] + bias) * sc;
    }
}

// ---------------- K_gram: symmetric 64x64 tiles -------------------------------
#define BT 64
#define BK 32
__global__ void __launch_bounds__(256) k_gram(const float* __restrict__ H) {
    const int TI[3] = {0, 0, 1};
    const int TJ[3] = {0, 1, 1};
    int b = blockIdx.y;
    int t = blockIdx.x;
    int ti = TI[t], tj = TJ[t];
    int i0 = ti * BT, j0 = tj * BT;
    int n = g_n0[b] + g_n1[b];
    if (i0 >= n || j0 >= n) return;
    __shared__ __align__(16) float sA[BK * (BT + 4)];
    __shared__ __align__(16) float sB[BK * (BT + 4)];
    int tid = threadIdx.x;
    int tx = tid & 15, ty = tid >> 4;
    float acc[4][4] = {};
    const float* Hb = H + (size_t)b * LL * HID;
    int lr = tid >> 3;
    int lc = tid & 7;
    for (int k0 = 0; k0 < HID; k0 += BK) {
#pragma unroll
        for (int h = 0; h < 2; h++) {
            int row = lr + 32 * h;
            float4 v = *(const float4*)(Hb + (size_t)(i0 + row) * HID + k0 + lc * 4);
            sA[(lc * 4 + 0) * (BT + 4) + row] = v.x;
            sA[(lc * 4 + 1) * (BT + 4) + row] = v.y;
            sA[(lc * 4 + 2) * (BT + 4) + row] = v.z;
            sA[(lc * 4 + 3) * (BT + 4) + row] = v.w;
            float4 u = *(const float4*)(Hb + (size_t)(j0 + row) * HID + k0 + lc * 4);
            sB[(lc * 4 + 0) * (BT + 4) + row] = u.x;
            sB[(lc * 4 + 1) * (BT + 4) + row] = u.y;
            sB[(lc * 4 + 2) * (BT + 4) + row] = u.z;
            sB[(lc * 4 + 3) * (BT + 4) + row] = u.w;
        }
        __syncthreads();
#pragma unroll
        for (int kk = 0; kk < BK; kk++) {
            float4 av = *(const float4*)&sA[kk * (BT + 4) + ty * 4];
            float4 bv = *(const float4*)&sB[kk * (BT + 4) + tx * 4];
            float ar[4] = {av.x, av.y, av.z, av.w};
            float br[4] = {bv.x, bv.y, bv.z, bv.w};
#pragma unroll
            for (int r = 0; r < 4; r++)
#pragma unroll
                for (int c = 0; c < 4; c++) acc[r][c] += ar[r] * br[c];
        }
        __syncthreads();
    }
    const float* sqb = g_sq + b * LL;
    float* out = g_Cs + (size_t)b * LL * LL;
#pragma unroll
    for (int r = 0; r < 4; r++) {
        int i = i0 + ty * 4 + r;
        float si = sqb[i];
#pragma unroll
        for (int c = 0; c < 4; c++) {
            int j = j0 + tx * 4 + c;
            float d2 = si + sqb[j] - 2.f * acc[r][c];
            float v = sqrtf(fmaxf(d2, 1e-6f)) * (L2E / EPSV);
            out[i * LL + j] = v;
            if (ti != tj) out[j * LL + i] = v;
        }
    }
}

// ---------------- K_sink: register-resident rows, block-unrolled --------------
// Thread covers f4 slots [slot0, slot0 + nblk*2) of its row; C holds them.
template<int MAXB>
__device__ __forceinline__ void load_row_regs(float4* C, const float* base, int cstride,
                                              int width, int nblk, int slot0, bool active) {
#pragma unroll
    for (int bq = 0; bq < MAXB; bq++) {
        if (bq < nblk) {
#pragma unroll
            for (int q = 0; q < 2; q++) {
                int c0 = 4 * (slot0 + bq * 2 + q);
                float4 v;
                v.x = (active && c0 + 0 < width) ? base[(c0 + 0) * cstride] : INFN;
                v.y = (active && c0 + 1 < width) ? base[(c0 + 1) * cstride] : INFN;
                v.z = (active && c0 + 2 < width) ? base[(c0 + 2) * cstride] : INFN;
                v.w = (active && c0 + 3 < width) ? base[(c0 + 3) * cstride] : INFN;
                C[bq * 2 + q] = v;
            }
        }
    }
}

// out[row] = coef - log2 sum_j 2^(u[j] - C[row][j]) (max-stabilized), row-split SP
template<int MAXB, int SP>
__device__ __forceinline__ void reg_pass(const float4* C, int nblk,
                                         const float4* __restrict__ u4slice,
                                         float* __restrict__ outv,
                                         float coef, int row, int part, bool active) {
    float m = -INFN;
#pragma unroll
    for (int bq = 0; bq < MAXB; bq++) {
        if (bq < nblk) {
            float4 u0 = u4slice[bq * 2 + 0], c0 = C[bq * 2 + 0];
            float4 u1 = u4slice[bq * 2 + 1], c1 = C[bq * 2 + 1];
            float t0 = fmaxf(fmaxf(u0.x - c0.x, u0.y - c0.y), fmaxf(u0.z - c0.z, u0.w - c0.w));
            float t1 = fmaxf(fmaxf(u1.x - c1.x, u1.y - c1.y), fmaxf(u1.z - c1.z, u1.w - c1.w));
            m = fmaxf(m, fmaxf(t0, t1));
        }
    }
    float s = 0.f;
#pragma unroll
    for (int bq = 0; bq < MAXB; bq++) {
        if (bq < nblk) {
            float4 u0 = u4slice[bq * 2 + 0], c0 = C[bq * 2 + 0];
            float4 u1 = u4slice[bq * 2 + 1], c1 = C[bq * 2 + 1];
            float s0 = ex2a(u0.x - c0.x - m) + ex2a(u0.y - c0.y - m)
                     + ex2a(u0.z - c0.z - m) + ex2a(u0.w - c0.w - m);
            float s1 = ex2a(u1.x - c1.x - m) + ex2a(u1.y - c1.y - m)
                     + ex2a(u1.z - c1.z - m) + ex2a(u1.w - c1.w - m);
            s += s0 + s1;
        }
    }
#pragma unroll
    for (int o = 1; o < SP; o <<= 1) {
        float om = __shfl_xor_sync(0xffffffffu, m, o);
        float os = __shfl_xor_sync(0xffffffffu, s, o);
        float nm = fmaxf(m, om);
        s = s * ex2a(m - nm) + os * ex2a(om - nm);
        m = nm;
    }
    if (active && part == 0) outv[row] = coef - (m + lg2a(s));
}

__global__ void __launch_bounds__(STH) k_sink(
        const float* __restrict__ lnw, const float* __restrict__ lnb,
        const float* __restrict__ Wcls, const float* __restrict__ bcls,
        float* __restrict__ out) {
    __shared__ __align__(16) float s_u[128], s_w[128];
    __shared__ float s_red[2 * (STH / 32)];
    __shared__ int s_last;
    int bx = blockIdx.x;
    int vg = bx >> 6;                // 0,1,2 -> v 2,0,1 (largest first)
    int b = bx & 63;
    int v = (vg == 0) ? 2 : (vg == 1) ? 0 : 1;
    int n0 = g_n0[b], n1 = g_n1[b];
    int tid = threadIdx.x;
    const float* src = g_Cs + (size_t)b * LL * LL;
    const float4* u4 = (const float4*)s_u;
    const float4* w4 = (const float4*)s_w;
    if (tid < 128) { s_u[tid] = 0.f; s_w[tid] = 0.f; }
    __syncthreads();

    int na, nb;
    float la2, lb2;
    if (v == 0) { na = n0; nb = n1; }
    else if (v == 1) { na = n0; nb = n0; }
    else { na = n1; nb = n1; }
    la2 = -lg2a((float)na);
    lb2 = -lg2a((float)nb);
    // state init: s_u = lb2 on [0,nb)
    if (tid < 128) s_u[tid] = (tid < nb) ? lb2 : 0.f;
    __syncthreads();

    if (v == 0) {
        // A: na x nb (rows type0, cols type1), SP=4, block covers 8 f4
        // T: nb x na (rows type1, cols type0), SP=2, block covers 4 f4
        int nb4 = (nb + 3) >> 2, na4 = (na + 3) >> 2;
        int nblkA = (nb4 + 7) >> 3;      // <= 4
        int nblkT = (na4 + 3) >> 2;      // <= 3
        int rowA = tid >> 2, partA = tid & 3;
        int rowT = tid >> 1, partT = tid & 1;
        bool actA = rowA < na, actT = rowT < nb;
        int rAc = actA ? rowA : 0, rTc = actT ? rowT : 0;
        float4 CA[8], CT[6];
        load_row_regs<4>(CA, src + rAc * LL + n0, 1, nb, nblkA, partA * nblkA * 2, actA);
        load_row_regs<3>(CT, src + n0 + rTc, LL, na, nblkT, partT * nblkT * 2, actT);
        for (int it = 0; it < NIT; it++) {
            reg_pass<4, 4>(CA, nblkA, u4 + partA * nblkA * 2, s_w, la2, rowA, partA, actA);
            __syncthreads();
            reg_pass<3, 2>(CT, nblkT, w4 + partT * nblkT * 2, s_u, lb2, rowT, partT, actT);
            __syncthreads();
        }
    } else if (v == 1) {
        // symmetric n0 x n0, SP=4, block covers 8 f4
        int n4 = (na + 3) >> 2;
        int nblk = (n4 + 7) >> 3;        // <= 2
        int row = tid >> 2, part = tid & 3;
        bool act = row < na;
        int rc = act ? row : 0;
        float4 C[4];
        load_row_regs<2>(C, src + rc * LL, 1, na, nblk, part * nblk * 2, act);
        for (int it = 0; it < NIT; it++) {
            reg_pass<2, 4>(C, nblk, u4 + part * nblk * 2, s_w, la2, row, part, act);
            __syncthreads();
            reg_pass<2, 4>(C, nblk, w4 + part * nblk * 2, s_u, lb2, row, part, act);
            __syncthreads();
        }
    } else {
        // symmetric n1 x n1, SP=2, block covers 4 f4
        int n4 = (na + 3) >> 2;
        int nblk = (n4 + 3) >> 2;        // <= 7
        int row = tid >> 1, part = tid & 1;
        bool act = row < na;
        int rc = act ? row : 0;
        float4 C[14];
        load_row_regs<7>(C, src + (n0 + rc) * LL + n0, 1, na, nblk, part * nblk * 2, act);
        for (int it = 0; it < NIT; it++) {
            reg_pass<7, 2>(C, nblk, u4 + part * nblk * 2, s_w, la2, row, part, act);
            __syncthreads();
            reg_pass<7, 2>(C, nblk, w4 + part * nblk * 2, s_u, lb2, row, part, act);
            __syncthreads();
        }
    }

    float val = 0.f;
    if (tid < na) val += (s_w[tid] - la2) * (1.f / (float)na);
    if (tid < nb) val += (s_u[tid] - lb2) * (1.f / (float)nb);
    val *= (EPSV / L2E);
#pragma unroll
    for (int o = 16; o; o >>= 1) val += __shfl_down_sync(0xffffffffu, val, o);
    int wid = tid >> 5;
    if ((tid & 31) == 0) s_red[wid] = val;
    __syncthreads();
    if (tid == 0) {
        float acc = 0.f;
#pragma unroll
        for (int i = 0; i < STH / 32; i++) acc += s_red[i];
        g_sink[v * BB + b] = acc;
        __threadfence();
        int old = atomicAdd(&g_cnt[b], 1);
        s_last = (old == 2) ? 1 : 0;
    }
    __syncthreads();
    if (!s_last) return;
    __threadfence();
    // ---- fused final head for batch b ----
    __shared__ float s_feat[FEAT];
    float dot = g_sink[b] - 0.5f * (g_sink[BB + b] + g_sink[2 * BB + b]);
    for (int i = tid; i < FEAT; i += STH)
        s_feat[i] = (i < NOUT) ? g_fused[b * NOUT + i] : dot;
    __syncthreads();
    float s = 0.f, s2 = 0.f;
    for (int i = tid; i < FEAT; i += STH) {
        float x = s_feat[i];
        s += x; s2 += x * x;
    }
#pragma unroll
    for (int o = 16; o; o >>= 1) {
        s  += __shfl_down_sync(0xffffffffu, s, o);
        s2 += __shfl_down_sync(0xffffffffu, s2, o);
    }
    if ((tid & 31) == 0) { s_red[wid] = s; s_red[STH / 32 + wid] = s2; }
    __syncthreads();
    float S = 0.f, S2 = 0.f;
#pragma unroll
    for (int i = 0; i < STH / 32; i++) { S += s_red[i]; S2 += s_red[STH / 32 + i]; }
    float mu = S / (float)FEAT;
    float var = S2 / (float)FEAT - mu * mu;
    float rstd = rsqrtf(var + 1e-5f);
    float a0 = 0.f, a1 = 0.f;
    for (int i = tid; i < FEAT; i += STH) {
        float h = (s_feat[i] - mu) * rstd * lnw[i] + lnb[i];
        a0 += h * Wcls[i];
        a1 += h * Wcls[FEAT + i];
    }
#pragma unroll
    for (int o = 16; o; o >>= 1) {
        a0 += __shfl_down_sync(0xffffffffu, a0, o);
        a1 += __shfl_down_sync(0xffffffffu, a1, o);
    }
    __syncthreads();
    if ((tid & 31) == 0) { s_red[wid] = a0; s_red[STH / 32 + wid] = a1; }
    __syncthreads();
    if (tid == 0) {
        float r0 = 0.f, r1 = 0.f;
#pragma unroll
        for (int i = 0; i < STH / 32; i++) { r0 += s_red[i]; r1 += s_red[STH / 32 + i]; }
        out[b * 2 + 0] = r0 + bcls[0];
        out[b * 2 + 1] = r1 + bcls[1];
    }
}

// ---------------- launch --------------------------------------------------------
extern "C" void kernel_launch(void* const* d_in, const int* in_sizes, int n_in,
                              void* d_out, int out_size) {
    const float* H    = (const float*)d_in[0];
    const int*   tt   = (const int*)d_in[1];
    const int*   am   = (const int*)d_in[2];
    const float* Wc   = (const float*)d_in[3];
    const float* bc   = (const float*)d_in[4];
    const float* Ws   = (const float*)d_in[5];
    const float* bs   = (const float*)d_in[6];
    const float* gate = (const float*)d_in[7];
    const float* lnw  = (const float*)d_in[8];
    const float* lnb  = (const float*)d_in[9];
    const float* Wcls = (const float*)d_in[10];
    const float* bcls = (const float*)d_in[11];
    float* out = (float*)d_out;

    k_prep<<<dim3(BB, 6), 128>>>(H, tt, am);
    k_gram<<<dim3(3, BB), 256>>>(H);
    k_fused<<<dim3(40, BB / FB), 256>>>(Wc, bc, Ws, bs, gate);
    k_sink<<<3 * BB, STH>>>(lnw, lnb, Wcls, bcls, out);
}